// round 2
// baseline (speedup 1.0000x reference)
#include <cuda_runtime.h>
#include <cuda_bf16.h>

#define NIDS 33               // ids 0..32 (0 = background)
#define NBINS (NIDS * NIDS)   // 1089

// Scratch: joint histogram hist[p*33 + t]  (no cudaMalloc allowed)
__device__ int g_hist[NBINS];

__global__ void zero_hist_kernel() {
    int i = blockIdx.x * blockDim.x + threadIdx.x;
    if (i < NBINS) g_hist[i] = 0;
}

__global__ void hist_kernel(const float4* __restrict__ pred4,
                            const float4* __restrict__ true4,
                            int n4,
                            const float* __restrict__ pred,
                            const float* __restrict__ truem,
                            int n) {
    __shared__ int sh[NBINS];
    for (int i = threadIdx.x; i < NBINS; i += blockDim.x) sh[i] = 0;
    __syncthreads();

    int gid    = blockIdx.x * blockDim.x + threadIdx.x;
    int stride = gridDim.x * blockDim.x;

    for (int i = gid; i < n4; i += stride) {
        float4 p = pred4[i];
        float4 t = true4[i];
        int p0 = (int)p.x, p1 = (int)p.y, p2 = (int)p.z, p3 = (int)p.w;
        int t0 = (int)t.x, t1 = (int)t.y, t2 = (int)t.z, t3 = (int)t.w;
        atomicAdd(&sh[p0 * NIDS + t0], 1);
        atomicAdd(&sh[p1 * NIDS + t1], 1);
        atomicAdd(&sh[p2 * NIDS + t2], 1);
        atomicAdd(&sh[p3 * NIDS + t3], 1);
    }
    // tail (n not divisible by 4)
    for (int i = n4 * 4 + gid; i < n; i += stride) {
        int p = (int)pred[i];
        int t = (int)truem[i];
        atomicAdd(&sh[p * NIDS + t], 1);
    }

    __syncthreads();
    for (int i = threadIdx.x; i < NBINS; i += blockDim.x) {
        int v = sh[i];
        if (v) atomicAdd(&g_hist[i], v);
    }
}

// Single block, 128 threads.
__global__ void finalize_kernel(float* __restrict__ out) {
    __shared__ int   h[NBINS];
    __shared__ float psum[NIDS];
    __shared__ float tsum[NIDS];
    __shared__ float part[NIDS];

    int tid = threadIdx.x;
    for (int i = tid; i < NBINS; i += blockDim.x) h[i] = g_hist[i];
    __syncthreads();

    if (tid < NIDS) {
        int s = 0;
        #pragma unroll
        for (int m = 0; m < NIDS; m++) s += h[tid * NIDS + m];
        psum[tid] = (float)s;
    } else if (tid >= 64 && tid < 64 + NIDS) {
        int m = tid - 64;
        int s = 0;
        #pragma unroll
        for (int nn = 0; nn < NIDS; nn++) s += h[nn * NIDS + m];
        tsum[m] = (float)s;
    }
    __syncthreads();

    if (tid >= 1 && tid <= 32) {
        int n = tid;
        float pn = psum[n];
        float max_iou = 0.0f;
        #pragma unroll
        for (int m = 1; m < NIDS; m++) {
            float inter = (float)h[n * NIDS + m];
            float uni   = pn + tsum[m] - inter;
            float iou   = (uni > 0.0f) ? (inter / uni) : 0.0f;
            max_iou = fmaxf(max_iou, iou);
        }
        part[n] = 1.0f - max_iou;
    }
    __syncthreads();

    if (tid == 0) {
        // loss = sum(1 - max_iou) + dummy
        float loss = 0.0f;
        for (int n = 1; n <= 32; n++) loss += part[n];
        // dummy = (sum of pred values + sum of true values) / 1e12
        double sp = 0.0, st = 0.0;
        for (int id = 0; id < NIDS; id++) {
            sp += (double)id * (double)psum[id];
            st += (double)id * (double)tsum[id];
        }
        loss += (float)((sp + st) * 1e-12);
        out[0] = loss;
    }
}

extern "C" void kernel_launch(void* const* d_in, const int* in_sizes, int n_in,
                              void* d_out, int out_size) {
    const float* pred = (const float*)d_in[0];
    const float* truem = (const float*)d_in[1];
    float* out = (float*)d_out;
    int n = in_sizes[0];
    int n4 = n / 4;

    zero_hist_kernel<<<(NBINS + 255) / 256, 256>>>();

    int threads = 256;
    int blocks  = 148 * 4;  // 148 SMs on B300; 4 CTAs each for latency hiding
    hist_kernel<<<blocks, threads>>>((const float4*)pred, (const float4*)truem, n4,
                                     pred, truem, n);

    finalize_kernel<<<1, 128>>>(out);
}

// round 3
// speedup vs baseline: 1.0977x; 1.0977x over previous
#include <cuda_runtime.h>
#include <cuda_bf16.h>

#define NIDS 33               // ids 0..32 (0 = background)
#define NBINS (NIDS * NIDS)   // 1089

// Scratch (no cudaMalloc allowed). Zero-initialized at module load; the
// finalizing block resets both after each call, so every kernel_launch
// (correctness run, capture, every replay) starts from zero state.
__device__ int          g_hist[NBINS];
__device__ unsigned int g_ticket;

__global__ void __launch_bounds__(256)
fused_iou_kernel(const float4* __restrict__ pred4,
                 const float4* __restrict__ true4,
                 int n4,
                 float* __restrict__ out,
                 int nblocks) {
    __shared__ int   sh[NBINS];
    __shared__ float psum[NIDS];
    __shared__ float tsum[NIDS];
    __shared__ float part[NIDS];
    __shared__ int   s_last;

    int tid = threadIdx.x;
    for (int i = tid; i < NBINS; i += blockDim.x) sh[i] = 0;
    __syncthreads();

    int gid    = blockIdx.x * blockDim.x + tid;
    int stride = gridDim.x * blockDim.x;

    // ---- joint histogram over pixels (unroll x2: 4 independent 16B loads) ----
    int i = gid;
    for (; i + stride < n4; i += 2 * stride) {
        float4 p0 = pred4[i];
        float4 t0 = true4[i];
        float4 p1 = pred4[i + stride];
        float4 t1 = true4[i + stride];
        atomicAdd(&sh[(int)p0.x * NIDS + (int)t0.x], 1);
        atomicAdd(&sh[(int)p0.y * NIDS + (int)t0.y], 1);
        atomicAdd(&sh[(int)p0.z * NIDS + (int)t0.z], 1);
        atomicAdd(&sh[(int)p0.w * NIDS + (int)t0.w], 1);
        atomicAdd(&sh[(int)p1.x * NIDS + (int)t1.x], 1);
        atomicAdd(&sh[(int)p1.y * NIDS + (int)t1.y], 1);
        atomicAdd(&sh[(int)p1.z * NIDS + (int)t1.z], 1);
        atomicAdd(&sh[(int)p1.w * NIDS + (int)t1.w], 1);
    }
    if (i < n4) {
        float4 p0 = pred4[i];
        float4 t0 = true4[i];
        atomicAdd(&sh[(int)p0.x * NIDS + (int)t0.x], 1);
        atomicAdd(&sh[(int)p0.y * NIDS + (int)t0.y], 1);
        atomicAdd(&sh[(int)p0.z * NIDS + (int)t0.z], 1);
        atomicAdd(&sh[(int)p0.w * NIDS + (int)t0.w], 1);
    }

    __syncthreads();
    // flush block-private histogram to global
    for (int b = tid; b < NBINS; b += blockDim.x) {
        int v = sh[b];
        if (v) atomicAdd(&g_hist[b], v);
    }
    __threadfence();

    // ---- ticket: last arriving block does the O(33x33) finalize ----
    if (tid == 0) {
        unsigned int t = atomicAdd(&g_ticket, 1u);
        s_last = (t == (unsigned int)(nblocks - 1));
    }
    __syncthreads();
    if (!s_last) return;

    // Pull the full histogram (atomics landed in L2; this SM has no stale
    // L1 copies of g_hist — it never plain-loaded it, and fences above order
    // the flushes before the ticket increment).
    for (int b = tid; b < NBINS; b += blockDim.x) sh[b] = g_hist[b];
    __syncthreads();

    if (tid < NIDS) {
        int s = 0;
        #pragma unroll
        for (int m = 0; m < NIDS; m++) s += sh[tid * NIDS + m];
        psum[tid] = (float)s;
    } else if (tid >= 64 && tid < 64 + NIDS) {
        int m = tid - 64;
        int s = 0;
        #pragma unroll
        for (int nn = 0; nn < NIDS; nn++) s += sh[nn * NIDS + m];
        tsum[m] = (float)s;
    }
    __syncthreads();

    if (tid >= 1 && tid <= 32) {
        float pn = psum[tid];
        float max_iou = 0.0f;
        #pragma unroll
        for (int m = 1; m < NIDS; m++) {
            float inter = (float)sh[tid * NIDS + m];
            float uni   = pn + tsum[m] - inter;
            float iou   = (uni > 0.0f) ? (inter / uni) : 0.0f;
            max_iou = fmaxf(max_iou, iou);
        }
        part[tid] = 1.0f - max_iou;
    }
    __syncthreads();

    if (tid == 0) {
        float loss = 0.0f;
        for (int n = 1; n <= 32; n++) loss += part[n];
        // dummy = (sum of all pred values + sum of all true values) / 1e12
        double sp = 0.0, st = 0.0;
        for (int id = 1; id < NIDS; id++) {
            sp += (double)id * (double)psum[id];
            st += (double)id * (double)tsum[id];
        }
        loss += (float)((sp + st) * 1e-12);
        out[0] = loss;
        g_ticket = 0u;   // reset for next call
    }
    // reset histogram for next call
    for (int b = tid; b < NBINS; b += blockDim.x) g_hist[b] = 0;
}

extern "C" void kernel_launch(void* const* d_in, const int* in_sizes, int n_in,
                              void* d_out, int out_size) {
    const float* pred  = (const float*)d_in[0];
    const float* truem = (const float*)d_in[1];
    float* out = (float*)d_out;
    int n  = in_sizes[0];
    int n4 = n / 4;   // n = 2048*2048, divisible by 4

    int threads = 256;
    int blocks  = 148 * 4;  // one wave at occupancy 4 on 148 SMs
    fused_iou_kernel<<<blocks, threads>>>((const float4*)pred,
                                          (const float4*)truem,
                                          n4, out, blocks);
}